// round 12
// baseline (speedup 1.0000x reference)
#include <cuda_runtime.h>
#include <cuda_bf16.h>
#include <math.h>
#include <math_constants.h>
#include <mma.h>

using namespace nvcuda;

#define NLAYER 12
#define NHEAD  12
#define CDIM   768
#define HSZ    64
#define VOCAB  50304
#define BBATCH 2
#define TSEQ   1024
#define NTOK   (BBATCH * TSEQ)
#define C3     (3 * CDIM)
#define C4     (4 * CDIM)
#define MINKEEP 64

typedef __nv_bfloat16 bf16;

// ---------------- static device scratch ----------------
__device__ float g_x[NTOK * CDIM];
__device__ float g_score[(long)BBATCH * NHEAD * TSEQ * TSEQ];
__device__ bf16  g_h_hi[NTOK * CDIM],  g_h_lo[NTOK * CDIM];
__device__ bf16  g_qkv_hi[NTOK * C3],  g_qkv_lo[NTOK * C3];
__device__ bf16  g_att_hi[(long)BBATCH * NHEAD * TSEQ * TSEQ];
__device__ bf16  g_att_lo[(long)BBATCH * NHEAD * TSEQ * TSEQ];
__device__ bf16  g_y_hi[NTOK * CDIM],  g_y_lo[NTOK * CDIM];
__device__ bf16  g_fc_hi[NTOK * C4],   g_fc_lo[NTOK * C4];
__device__ bf16  g_aw_hi[NLAYER * CDIM * C3],   g_aw_lo[NLAYER * CDIM * C3];
__device__ bf16  g_pw_hi[NLAYER * CDIM * CDIM], g_pw_lo[NLAYER * CDIM * CDIM];
__device__ bf16  g_fw_hi[NLAYER * CDIM * C4],   g_fw_lo[NLAYER * CDIM * C4];
__device__ bf16  g_mw_hi[NLAYER * C4 * CDIM],   g_mw_lo[NLAYER * C4 * CDIM];
__device__ bf16  g_wte_hi[VOCAB * CDIM],        g_wte_lo[VOCAB * CDIM];
__device__ float g_am[NTOK];
__device__ float g_imp[NTOK];
__device__ float g_nll[NTOK];

__device__ __forceinline__ void split_f32(float v, bf16& h, bf16& l) {
    h = __float2bfloat16_rn(v);
    l = __float2bfloat16_rn(v - __bfloat162float(h));
}

// ---------------- cp.async helpers ----------------
__device__ __forceinline__ void cp_async16(void* d, const void* s) {
    asm volatile("cp.async.cg.shared.global [%0], [%1], 16;" ::
        "r"((unsigned)__cvta_generic_to_shared(d)), "l"(s));
}
__device__ __forceinline__ void cp_commit() { asm volatile("cp.async.commit_group;"); }
template<int N> __device__ __forceinline__ void cp_wait() {
    asm volatile("cp.async.wait_group %0;" :: "n"(N));
}

// ---------------- weight split: fp32 -> (hi, lo) bf16 ----------------
__global__ void split_kernel(const float4* __restrict__ in, bf16* __restrict__ hi,
                             bf16* __restrict__ lo, int n4)
{
    int i = blockIdx.x * 256 + threadIdx.x;
    if (i >= n4) return;
    float4 v = in[i];
    bf16 h0, l0, h1, l1, h2, l2, h3, l3;
    split_f32(v.x, h0, l0); split_f32(v.y, h1, l1);
    split_f32(v.z, h2, l2); split_f32(v.w, h3, l3);
    long o = (long)i * 4;
    hi[o] = h0; hi[o+1] = h1; hi[o+2] = h2; hi[o+3] = h3;
    lo[o] = l0; lo[o+1] = l1; lo[o+2] = l2; lo[o+3] = l3;
}

// ---------------- bf16 x3 compensated tensor-core GEMM, cp.async 2-stage ----------------
// C = A*B, A/B pre-split (hi,lo) bf16. A: M x K row-major (lda).
// B: K x N (ldb) if !TRANSB, else stored N x K (ldb).
// Requires: M % 128 == 0, N % BN == 0, K % 32 == 0.
// causal: skip tiles with blockIdx.x > blockIdx.y (upper triangle, BN==BM).
// trik:   clamp K to (blockIdx.y+1)*BM (probs beyond causal bound are exactly 0).
#define BM 128
#define BKK 32
#define APITCH 40

template <bool TRANSB, int ACT, bool SPLITOUT, int BN>
__global__ __launch_bounds__(256) void gemm_bf3(
    const bf16* __restrict__ Ah, const bf16* __restrict__ Al, int lda, long sA1, long sA2,
    const bf16* __restrict__ Bh, const bf16* __restrict__ Bl, int ldb, long sB1, long sB2,
    const float* __restrict__ bias, const float* resid,
    float* Cf, bf16* Chi, bf16* Clo, int ldc, long sC1, long sC2,
    int N, int K, int z2count, int causal, int trik)
{
    if (causal && blockIdx.x > blockIdx.y) return;
    if (trik) {
        int kl = (blockIdx.y + 1) * BM;
        if (kl < K) K = kl;
    }

    constexpr int BROWS  = TRANSB ? BN : BKK;
    constexpr int BPITCH = TRANSB ? APITCH : (BN + 8);
    constexpr int ASZ    = BM * APITCH;           // halves per A array per stage
    constexpr int BSZ    = BROWS * BPITCH;        // halves per B array per stage
    constexpr int STAGE  = 2 * ASZ + 2 * BSZ;     // halves per stage
    constexpr int NJ     = BN / 32;               // 16-wide j tiles per warp
    constexpr int EPP    = BN + 4;                // epilogue fp32 pitch

    extern __shared__ __align__(16) char smem_raw[];
    bf16* smem = (bf16*)smem_raw;
    float* Cs = (float*)smem_raw;

    int zb = blockIdx.z / z2count, zh = blockIdx.z % z2count;
    Ah += (long)zb * sA1 + (long)zh * sA2;
    Al += (long)zb * sA1 + (long)zh * sA2;
    Bh += (long)zb * sB1 + (long)zh * sB2;
    Bl += (long)zb * sB1 + (long)zh * sB2;
    long cofs = (long)zb * sC1 + (long)zh * sC2;

    const int by = blockIdx.y * BM;
    const int bx = blockIdx.x * BN;
    const int tid = threadIdx.x;
    const int wid = tid >> 5;
    const int wm = wid & 3;     // 4 row groups of 32
    const int wn = wid >> 2;    // 2 col groups of BN/2

    wmma::fragment<wmma::accumulator, 16, 16, 16, float> acc[2][NJ];
    #pragma unroll
    for (int i = 0; i < 2; i++)
        #pragma unroll
        for (int j = 0; j < NJ; j++)
            wmma::fill_fragment(acc[i][j], 0.0f);

    // ---- async stage loader: copies 32-K chunk k0 into stage stg ----
    auto load_stage = [&](int k0, int stg) {
        bf16* sAh = smem + stg * STAGE;
        bf16* sAl = sAh + ASZ;
        bf16* sBh = sAl + ASZ;
        bf16* sBl = sBh + BSZ;
        // A: 128 rows x 32 halves, 2 x 16B per thread per array
        #pragma unroll
        for (int i = 0; i < 2; i++) {
            int idx = tid + i * 256;
            int r = idx >> 2, v = idx & 3;
            long off = (long)(by + r) * lda + k0 + v * 8;
            cp_async16(sAh + r * APITCH + v * 8, Ah + off);
            cp_async16(sAl + r * APITCH + v * 8, Al + off);
        }
        if (!TRANSB) {
            // B: 32 rows x BN halves
            constexpr int VPR = BN / 8;          // 16B vectors per row
            constexpr int ITER = (BKK * VPR) / 256;
            #pragma unroll
            for (int i = 0; i < (ITER > 0 ? ITER : 1); i++) {
                int idx = tid + i * 256;
                int kr = idx / VPR, v = idx % VPR;
                long off = (long)(k0 + kr) * ldb + bx + v * 8;
                cp_async16(sBh + kr * BPITCH + v * 8, Bh + off);
                cp_async16(sBl + kr * BPITCH + v * 8, Bl + off);
            }
        } else {
            // B: BN rows x 32 halves
            #pragma unroll
            for (int i = 0; i < BN / 64; i++) {
                int idx = tid + i * 256;
                int n = idx >> 2, v = idx & 3;
                long off = (long)(bx + n) * ldb + k0 + v * 8;
                cp_async16(sBh + n * BPITCH + v * 8, Bh + off);
                cp_async16(sBl + n * BPITCH + v * 8, Bl + off);
            }
        }
        cp_commit();
    };

    // ---- mma over one staged 32-K chunk ----
    auto do_mma = [&](int stg) {
        bf16* sAh = smem + stg * STAGE;
        bf16* sAl = sAh + ASZ;
        bf16* sBh = sAl + ASZ;
        bf16* sBl = sBh + BSZ;
        #pragma unroll
        for (int ks = 0; ks < 2; ks++) {
            wmma::fragment<wmma::matrix_a, 16, 16, 16, bf16, wmma::row_major> fah[2], fal[2];
            #pragma unroll
            for (int i = 0; i < 2; i++) {
                int m0 = wm * 32 + i * 16;
                wmma::load_matrix_sync(fah[i], sAh + m0 * APITCH + ks * 16, APITCH);
                wmma::load_matrix_sync(fal[i], sAl + m0 * APITCH + ks * 16, APITCH);
            }
            if (!TRANSB) {
                wmma::fragment<wmma::matrix_b, 16, 16, 16, bf16, wmma::row_major> fbh, fbl;
                #pragma unroll
                for (int j = 0; j < NJ; j++) {
                    int n0 = wn * (BN / 2) + j * 16;
                    wmma::load_matrix_sync(fbh, sBh + ks * 16 * BPITCH + n0, BPITCH);
                    wmma::load_matrix_sync(fbl, sBl + ks * 16 * BPITCH + n0, BPITCH);
                    #pragma unroll
                    for (int i = 0; i < 2; i++) {
                        wmma::mma_sync(acc[i][j], fah[i], fbl, acc[i][j]);
                        wmma::mma_sync(acc[i][j], fal[i], fbh, acc[i][j]);
                        wmma::mma_sync(acc[i][j], fah[i], fbh, acc[i][j]);
                    }
                }
            } else {
                wmma::fragment<wmma::matrix_b, 16, 16, 16, bf16, wmma::col_major> fbh, fbl;
                #pragma unroll
                for (int j = 0; j < NJ; j++) {
                    int n0 = wn * (BN / 2) + j * 16;
                    wmma::load_matrix_sync(fbh, sBh + n0 * BPITCH + ks * 16, BPITCH);
                    wmma::load_matrix_sync(fbl, sBl + n0 * BPITCH + ks * 16, BPITCH);
                    #pragma unroll
                    for (int i = 0; i < 2; i++) {
                        wmma::mma_sync(acc[i][j], fah[i], fbl, acc[i][j]);
                        wmma::mma_sync(acc[i][j], fal[i], fbh, acc[i][j]);
                        wmma::mma_sync(acc[i][j], fah[i], fbh, acc[i][j]);
                    }
                }
            }
        }
    };

    const int nk = K / BKK;
    load_stage(0, 0);
    if (nk > 1) load_stage(BKK, 1); else cp_commit();

    for (int i = 0; i < nk; i++) {
        if (i < nk - 1) cp_wait<1>(); else cp_wait<0>();
        __syncthreads();
        do_mma(i & 1);
        __syncthreads();
        if (i + 2 < nk) load_stage((i + 2) * BKK, i & 1);
    }

    // ---- epilogue: two 64-row waves through 64 x EPP fp32 staging ----
    #pragma unroll
    for (int wave = 0; wave < 2; wave++) {
        if ((wm >> 1) == wave) {
            int rbase = (wm & 1) * 32;
            #pragma unroll
            for (int i = 0; i < 2; i++)
                #pragma unroll
                for (int j = 0; j < NJ; j++)
                    wmma::store_matrix_sync(Cs + (rbase + i * 16) * EPP + wn * (BN / 2) + j * 16,
                                            acc[i][j], EPP, wmma::mem_row_major);
        }
        __syncthreads();
        constexpr int EITER = (64 * BN) / 256;
        #pragma unroll 4
        for (int e = 0; e < EITER; e++) {
            int idx = tid + e * 256;
            int r = idx / BN, n = idx % BN;
            int gn = bx + n;
            float v = Cs[r * EPP + n];
            if (bias) v += bias[gn];
            long off = cofs + (long)(by + wave * 64 + r) * ldc + gn;
            if (ACT == 1) v = 0.5f * v * (1.0f + erff(v * 0.70710678118654752f));
            if (SPLITOUT) {
                bf16 h, l; split_f32(v, h, l);
                Chi[off] = h; Clo[off] = l;
            } else {
                if (resid) v += resid[off];
                Cf[off] = v;
            }
        }
        __syncthreads();
    }
}

// host-side smem size mirror
static inline int gemm_smem_bytes(bool transb, int bn) {
    int bsz = transb ? bn * APITCH : BKK * (bn + 8);
    int stage = 2 * BM * APITCH + 2 * bsz;
    return 2 * stage * 2;   // 2 stages, bf16
}

// ---------------- layernorm -> split bf16 ----------------
__global__ void ln_split_kernel(const float* __restrict__ x, const float* __restrict__ w,
                                const float* __restrict__ b, bf16* __restrict__ oh,
                                bf16* __restrict__ ol)
{
    int row = blockIdx.x;
    const float* xr = x + (long)row * CDIM;
    int tid = threadIdx.x;  // 256
    float v[3];
    float s = 0.f, s2 = 0.f;
    #pragma unroll
    for (int i = 0; i < 3; i++) {
        int c = tid + i * 256;
        float t = xr[c];
        v[i] = t; s += t; s2 += t * t;
    }
    __shared__ float r1[256], r2[256];
    r1[tid] = s; r2[tid] = s2;
    __syncthreads();
    for (int st = 128; st > 0; st >>= 1) {
        if (tid < st) { r1[tid] += r1[tid + st]; r2[tid] += r2[tid + st]; }
        __syncthreads();
    }
    float mean = r1[0] * (1.0f / CDIM);
    float var  = r2[0] * (1.0f / CDIM) - mean * mean;
    float rstd = rsqrtf(var + 1e-5f);
    #pragma unroll
    for (int i = 0; i < 3; i++) {
        int c = tid + i * 256;
        float o = (v[i] - mean) * rstd * w[c] + b[c];
        bf16 h, l; split_f32(o, h, l);
        oh[(long)row * CDIM + c] = h;
        ol[(long)row * CDIM + c] = l;
    }
}

// ---------------- embedding / init ----------------
__global__ void embed_kernel(const int* __restrict__ idx, const float* __restrict__ wte,
                             const float* __restrict__ wpe, float* __restrict__ x)
{
    int row = blockIdx.x;
    int t = row % TSEQ;
    int tok = idx[row];
    const float* we = wte + (long)tok * CDIM;
    const float* wp = wpe + (long)t * CDIM;
    float* xr = x + (long)row * CDIM;
    for (int c = threadIdx.x; c < CDIM; c += 256)
        xr[c] = we[c] + wp[c];
}

__global__ void init_am_kernel(float* am)
{
    int i = blockIdx.x * 256 + threadIdx.x;
    if (i < NTOK) am[i] = 1.0f;
}

__global__ void zero_kernel(float* p, int n)
{
    int i = blockIdx.x * 256 + threadIdx.x;
    if (i < n) p[i] = 0.0f;
}

// ---------------- softmax (+scale+causal+key-mask) -> split bf16 probs ----------------
__global__ void softmax_mask_kernel(const float* __restrict__ score, const float* __restrict__ am,
                                    bf16* __restrict__ ah, bf16* __restrict__ al)
{
    long z = blockIdx.x;             // (b*H + h)*T + q
    int q = (int)(z % TSEQ);
    int b = (int)(z / ((long)NHEAD * TSEQ));
    const float* row = score + z * TSEQ;
    const float* amr = am + (long)b * TSEQ;
    int tid = threadIdx.x;  // 256

    float vals[4];
    float lmax = -CUDART_INF_F;
    #pragma unroll
    for (int i = 0; i < 4; i++) {
        int k = tid + i * 256;
        float sc = row[k] * 0.125f;
        bool valid = (k <= q) && (amr[k] > 0.0f);
        sc = valid ? sc : -CUDART_INF_F;
        vals[i] = sc;
        lmax = fmaxf(lmax, sc);
    }
    __shared__ float red[256];
    red[tid] = lmax;
    __syncthreads();
    for (int st = 128; st > 0; st >>= 1) {
        if (tid < st) red[tid] = fmaxf(red[tid], red[tid + st]);
        __syncthreads();
    }
    float m = red[0];
    __syncthreads();
    float lsum = 0.f;
    #pragma unroll
    for (int i = 0; i < 4; i++) {
        float e = expf(vals[i] - m);
        vals[i] = e;
        lsum += e;
    }
    red[tid] = lsum;
    __syncthreads();
    for (int st = 128; st > 0; st >>= 1) {
        if (tid < st) red[tid] += red[tid + st];
        __syncthreads();
    }
    float inv = 1.0f / red[0];
    #pragma unroll
    for (int i = 0; i < 4; i++) {
        int k = tid + i * 256;
        float p = vals[i] * inv;
        bf16 h, l; split_f32(p, h, l);
        ah[z * TSEQ + k] = h;
        al[z * TSEQ + k] = l;
    }
}

// ---------------- importance reduce ----------------
__global__ void imp_reduce_kernel(const bf16* __restrict__ ah, const bf16* __restrict__ al,
                                  float* __restrict__ imp)
{
    int b = blockIdx.x;
    int k = blockIdx.y * 256 + threadIdx.x;
    int q0 = blockIdx.z * (TSEQ / 16);
    float s = 0.f;
    for (int h = 0; h < NHEAD; h++) {
        long base = ((long)(b * NHEAD + h) * TSEQ) * TSEQ + k;
        #pragma unroll 4
        for (int q = q0; q < q0 + TSEQ / 16; q++) {
            long o = base + (long)q * TSEQ;
            s += __bfloat162float(ah[o]) + __bfloat162float(al[o]);
        }
    }
    atomicAdd(&imp[b * TSEQ + k], s);
}

// ---------------- pruning mask update / apply ----------------
__global__ void prune_mask_kernel(const float* __restrict__ imp, float* __restrict__ am,
                                  const float* __restrict__ thresholds, int layer)
{
    int i = blockIdx.x * 256 + threadIdx.x;
    if (i >= NTOK) return;
    int t = i % TSEQ;
    float th = thresholds[layer];
    float v = imp[i] * (1.0f / ((float)NHEAD * (float)TSEQ));
    float pm = (t >= TSEQ - MINKEEP) ? 1.0f : ((v >= th) ? 1.0f : 0.0f);  // NaN>=th -> false
    am[i] = am[i] * pm;
}

__global__ void scale_rows_kernel(float* __restrict__ x, const float* __restrict__ am)
{
    int row = blockIdx.x;
    float s = am[row];
    float* xr = x + (long)row * CDIM;
    for (int c = threadIdx.x; c < CDIM; c += 256)
        xr[c] *= s;
}

// ---------------- loss ----------------
__global__ void loss_row_kernel(const float* __restrict__ logits, const int* __restrict__ targets,
                                float* __restrict__ nll)
{
    int row = blockIdx.x;
    const float* lr = logits + (long)row * VOCAB;
    int tid = threadIdx.x;  // 256
    float m = -CUDART_INF_F;
    for (int c = tid; c < VOCAB; c += 256) m = fmaxf(m, lr[c]);
    __shared__ float red[256];
    red[tid] = m;
    __syncthreads();
    for (int st = 128; st > 0; st >>= 1) {
        if (tid < st) red[tid] = fmaxf(red[tid], red[tid + st]);
        __syncthreads();
    }
    m = red[0];
    __syncthreads();
    float s = 0.f;
    for (int c = tid; c < VOCAB; c += 256) s += expf(lr[c] - m);
    red[tid] = s;
    __syncthreads();
    for (int st = 128; st > 0; st >>= 1) {
        if (tid < st) red[tid] += red[tid + st];
        __syncthreads();
    }
    if (tid == 0) {
        int tgt = targets[row];
        float v = 0.f;
        if (tgt != -1) v = m + logf(red[0]) - lr[tgt];
        nll[row] = v;
    }
}

__global__ void loss_final_kernel(const float* __restrict__ nll, const int* __restrict__ targets,
                                  float* __restrict__ out)
{
    int tid = threadIdx.x;  // 256
    float s = 0.f, cnt = 0.f;
    for (int i = tid; i < NTOK; i += 256) {
        if (targets[i] != -1) { s += nll[i]; cnt += 1.f; }
    }
    __shared__ float r1[256], r2[256];
    r1[tid] = s; r2[tid] = cnt;
    __syncthreads();
    for (int st = 128; st > 0; st >>= 1) {
        if (tid < st) { r1[tid] += r1[tid + st]; r2[tid] += r2[tid + st]; }
        __syncthreads();
    }
    if (tid == 0) out[0] = r1[0] / r2[0];
}

// ---------------- host orchestration ----------------
extern "C" void kernel_launch(void* const* d_in, const int* in_sizes, int n_in,
                              void* d_out, int out_size)
{
    const int*   idx        = (const int*)d_in[0];
    const int*   targets    = (const int*)d_in[1];
    const float* wte        = (const float*)d_in[2];
    const float* wpe        = (const float*)d_in[3];
    const float* ln1_w      = (const float*)d_in[4];
    const float* ln1_b      = (const float*)d_in[5];
    const float* attn_w     = (const float*)d_in[6];
    const float* attn_b     = (const float*)d_in[7];
    const float* proj_w     = (const float*)d_in[8];
    const float* proj_b     = (const float*)d_in[9];
    const float* ln2_w      = (const float*)d_in[10];
    const float* ln2_b      = (const float*)d_in[11];
    const float* fc_w       = (const float*)d_in[12];
    const float* fc_b       = (const float*)d_in[13];
    const float* mlp_w      = (const float*)d_in[14];
    const float* mlp_b      = (const float*)d_in[15];
    const float* thresholds = (const float*)d_in[16];
    const float* lnf_w      = (const float*)d_in[17];
    const float* lnf_b      = (const float*)d_in[18];

    float *x, *score, *am, *imp, *nll;
    bf16 *hh, *hl, *qh, *ql, *atth, *attl, *yh, *yl, *fch, *fcl;
    bf16 *awh, *awl, *pwh, *pwl, *fwh, *fwl, *mwh, *mwl, *wteh, *wtel;
    cudaGetSymbolAddress((void**)&x,     g_x);
    cudaGetSymbolAddress((void**)&score, g_score);
    cudaGetSymbolAddress((void**)&am,    g_am);
    cudaGetSymbolAddress((void**)&imp,   g_imp);
    cudaGetSymbolAddress((void**)&nll,   g_nll);
    cudaGetSymbolAddress((void**)&hh,    g_h_hi);   cudaGetSymbolAddress((void**)&hl, g_h_lo);
    cudaGetSymbolAddress((void**)&qh,    g_qkv_hi); cudaGetSymbolAddress((void**)&ql, g_qkv_lo);
    cudaGetSymbolAddress((void**)&atth,  g_att_hi); cudaGetSymbolAddress((void**)&attl, g_att_lo);
    cudaGetSymbolAddress((void**)&yh,    g_y_hi);   cudaGetSymbolAddress((void**)&yl, g_y_lo);
    cudaGetSymbolAddress((void**)&fch,   g_fc_hi);  cudaGetSymbolAddress((void**)&fcl, g_fc_lo);
    cudaGetSymbolAddress((void**)&awh,   g_aw_hi);  cudaGetSymbolAddress((void**)&awl, g_aw_lo);
    cudaGetSymbolAddress((void**)&pwh,   g_pw_hi);  cudaGetSymbolAddress((void**)&pwl, g_pw_lo);
    cudaGetSymbolAddress((void**)&fwh,   g_fw_hi);  cudaGetSymbolAddress((void**)&fwl, g_fw_lo);
    cudaGetSymbolAddress((void**)&mwh,   g_mw_hi);  cudaGetSymbolAddress((void**)&mwl, g_mw_lo);
    cudaGetSymbolAddress((void**)&wteh,  g_wte_hi); cudaGetSymbolAddress((void**)&wtel, g_wte_lo);

    float* out = (float*)d_out;

    const int SM_NT  = gemm_smem_bytes(false, 128);  // 75776
    const int SM_T   = gemm_smem_bytes(true, 128);   // 81920
    const int SM_N64 = gemm_smem_bytes(false, 64);   // 59392

    static bool attr_done = false;
    if (!attr_done) {
        cudaFuncSetAttribute(gemm_bf3<false, 0, true, 128>, cudaFuncAttributeMaxDynamicSharedMemorySize, SM_NT);
        cudaFuncSetAttribute(gemm_bf3<false, 1, true, 128>, cudaFuncAttributeMaxDynamicSharedMemorySize, SM_NT);
        cudaFuncSetAttribute(gemm_bf3<false, 0, false, 128>, cudaFuncAttributeMaxDynamicSharedMemorySize, SM_NT);
        cudaFuncSetAttribute(gemm_bf3<true, 0, false, 128>, cudaFuncAttributeMaxDynamicSharedMemorySize, SM_T);
        cudaFuncSetAttribute(gemm_bf3<false, 0, true, 64>, cudaFuncAttributeMaxDynamicSharedMemorySize, SM_N64);
        attr_done = true;
    }

    // split all weights
    {
        int n;
        n = NLAYER * CDIM * C3 / 4;
        split_kernel<<<(n + 255) / 256, 256>>>((const float4*)attn_w, awh, awl, n);
        n = NLAYER * CDIM * CDIM / 4;
        split_kernel<<<(n + 255) / 256, 256>>>((const float4*)proj_w, pwh, pwl, n);
        n = NLAYER * CDIM * C4 / 4;
        split_kernel<<<(n + 255) / 256, 256>>>((const float4*)fc_w, fwh, fwl, n);
        n = NLAYER * C4 * CDIM / 4;
        split_kernel<<<(n + 255) / 256, 256>>>((const float4*)mlp_w, mwh, mwl, n);
        n = VOCAB * CDIM / 4;
        split_kernel<<<(n + 255) / 256, 256>>>((const float4*)wte, wteh, wtel, n);
    }

    embed_kernel<<<NTOK, 256>>>(idx, wte, wpe, x);
    init_am_kernel<<<NTOK / 256, 256>>>(am);

    for (int l = 0; l < NLAYER; l++) {
        ln_split_kernel<<<NTOK, 256>>>(x, ln1_w + (long)l * CDIM, ln1_b + (long)l * CDIM, hh, hl);

        // qkv = h @ attn_w + attn_b -> split out
        gemm_bf3<false, 0, true, 128><<<dim3(C3 / 128, NTOK / BM, 1), 256, SM_NT>>>(
            hh, hl, CDIM, 0, 0,
            awh + (long)l * CDIM * C3, awl + (long)l * CDIM * C3, C3, 0, 0,
            attn_b + (long)l * C3, nullptr,
            nullptr, qh, ql, C3, 0, 0, C3, CDIM, 1, 0, 0);

        // scores = Q K^T (fp32), batched over b*H — causal tile skip
        gemm_bf3<true, 0, false, 128><<<dim3(TSEQ / 128, TSEQ / BM, BBATCH * NHEAD), 256, SM_T>>>(
            qh, ql, C3, (long)TSEQ * C3, HSZ,
            qh + CDIM, ql + CDIM, C3, (long)TSEQ * C3, HSZ,
            nullptr, nullptr,
            score, nullptr, nullptr, TSEQ, (long)NHEAD * TSEQ * TSEQ, (long)TSEQ * TSEQ,
            TSEQ, HSZ, NHEAD, 1, 0);

        softmax_mask_kernel<<<BBATCH * NHEAD * TSEQ, 256>>>(score, am, atth, attl);

        zero_kernel<<<NTOK / 256, 256>>>(imp, NTOK);
        imp_reduce_kernel<<<dim3(BBATCH, TSEQ / 256, 16), 256>>>(atth, attl, imp);

        // y = att @ V -> split out (BN=64; triangular K clamp — probs beyond are exactly 0)
        gemm_bf3<false, 0, true, 64><<<dim3(1, TSEQ / BM, BBATCH * NHEAD), 256, SM_N64>>>(
            atth, attl, TSEQ, (long)NHEAD * TSEQ * TSEQ, (long)TSEQ * TSEQ,
            qh + 2 * CDIM, ql + 2 * CDIM, C3, (long)TSEQ * C3, HSZ,
            nullptr, nullptr,
            nullptr, yh, yl, CDIM, (long)TSEQ * CDIM, HSZ,
            HSZ, TSEQ, NHEAD, 0, 1);

        // x = x + y @ proj_w + proj_b (fp32)
        gemm_bf3<false, 0, false, 128><<<dim3(CDIM / 128, NTOK / BM, 1), 256, SM_NT>>>(
            yh, yl, CDIM, 0, 0,
            pwh + (long)l * CDIM * CDIM, pwl + (long)l * CDIM * CDIM, CDIM, 0, 0,
            proj_b + (long)l * CDIM, x,
            x, nullptr, nullptr, CDIM, 0, 0, CDIM, CDIM, 1, 0, 0);

        prune_mask_kernel<<<NTOK / 256, 256>>>(imp, am, thresholds, l);
        scale_rows_kernel<<<NTOK, 256>>>(x, am);

        ln_split_kernel<<<NTOK, 256>>>(x, ln2_w + (long)l * CDIM, ln2_b + (long)l * CDIM, hh, hl);

        // fc = gelu(h @ fc_w + fc_b) -> split out
        gemm_bf3<false, 1, true, 128><<<dim3(C4 / 128, NTOK / BM, 1), 256, SM_NT>>>(
            hh, hl, CDIM, 0, 0,
            fwh + (long)l * CDIM * C4, fwl + (long)l * CDIM * C4, C4, 0, 0,
            fc_b + (long)l * C4, nullptr,
            nullptr, fch, fcl, C4, 0, 0, C4, CDIM, 1, 0, 0);

        // x = x + fc @ mlp_w + mlp_b (fp32)
        gemm_bf3<false, 0, false, 128><<<dim3(CDIM / 128, NTOK / BM, 1), 256, SM_NT>>>(
            fch, fcl, C4, 0, 0,
            mwh + (long)l * C4 * CDIM, mwl + (long)l * C4 * CDIM, CDIM, 0, 0,
            mlp_b + (long)l * CDIM, x,
            x, nullptr, nullptr, CDIM, 0, 0, CDIM, C4, 1, 0, 0);
    }

    ln_split_kernel<<<NTOK, 256>>>(x, lnf_w, lnf_b, hh, hl);

    // logits = h @ wte^T (fp32 out)  — VOCAB = 50304 = 393 * 128, exact
    gemm_bf3<true, 0, false, 128><<<dim3(VOCAB / 128, NTOK / BM, 1), 256, SM_T>>>(
        hh, hl, CDIM, 0, 0,
        wteh, wtel, CDIM, 0, 0,
        nullptr, nullptr,
        out, nullptr, nullptr, VOCAB, 0, 0, VOCAB, CDIM, 1, 0, 0);

    loss_row_kernel<<<NTOK, 256>>>(out, targets, nll);
    if ((long)out_size >= (long)NTOK * VOCAB + 1)
        loss_final_kernel<<<1, 256>>>(nll, targets, out + (long)NTOK * VOCAB);
}

// round 13
// speedup vs baseline: 1.5018x; 1.5018x over previous
#include <cuda_runtime.h>
#include <cuda_bf16.h>
#include <math.h>
#include <math_constants.h>
#include <mma.h>

using namespace nvcuda;

#define NLAYER 12
#define NHEAD  12
#define CDIM   768
#define HSZ    64
#define VOCAB  50304
#define BBATCH 2
#define TSEQ   1024
#define NTOK   (BBATCH * TSEQ)
#define C3     (3 * CDIM)
#define C4     (4 * CDIM)
#define MINKEEP 64

typedef __nv_bfloat16 bf16;

// ---------------- static device scratch ----------------
__device__ float g_x[NTOK * CDIM];
__device__ float g_score[(long)BBATCH * NHEAD * TSEQ * TSEQ];
__device__ bf16  g_h_hi[NTOK * CDIM],  g_h_lo[NTOK * CDIM];
__device__ bf16  g_qkv_hi[NTOK * C3],  g_qkv_lo[NTOK * C3];
__device__ bf16  g_att_hi[(long)BBATCH * NHEAD * TSEQ * TSEQ];
__device__ bf16  g_att_lo[(long)BBATCH * NHEAD * TSEQ * TSEQ];
__device__ bf16  g_y_hi[NTOK * CDIM],  g_y_lo[NTOK * CDIM];
__device__ bf16  g_fc_hi[NTOK * C4],   g_fc_lo[NTOK * C4];
__device__ bf16  g_aw_hi[NLAYER * CDIM * C3],   g_aw_lo[NLAYER * CDIM * C3];
__device__ bf16  g_pw_hi[NLAYER * CDIM * CDIM], g_pw_lo[NLAYER * CDIM * CDIM];
__device__ bf16  g_fw_hi[NLAYER * CDIM * C4],   g_fw_lo[NLAYER * CDIM * C4];
__device__ bf16  g_mw_hi[NLAYER * C4 * CDIM],   g_mw_lo[NLAYER * C4 * CDIM];
__device__ bf16  g_wte_hi[VOCAB * CDIM],        g_wte_lo[VOCAB * CDIM];
__device__ float g_am[NTOK];
__device__ float g_imp[NTOK];
__device__ float g_nll[NTOK];

__device__ __forceinline__ void split_f32(float v, bf16& h, bf16& l) {
    h = __float2bfloat16_rn(v);
    l = __float2bfloat16_rn(v - __bfloat162float(h));
}

// ---------------- cp.async helpers ----------------
__device__ __forceinline__ void cp_async16(void* d, const void* s) {
    asm volatile("cp.async.cg.shared.global [%0], [%1], 16;" ::
        "r"((unsigned)__cvta_generic_to_shared(d)), "l"(s));
}
__device__ __forceinline__ void cp_commit() { asm volatile("cp.async.commit_group;"); }
template<int N> __device__ __forceinline__ void cp_wait() {
    asm volatile("cp.async.wait_group %0;" :: "n"(N));
}

// ---------------- weight split: fp32 -> (hi, lo) bf16 ----------------
__global__ void split_kernel(const float4* __restrict__ in, bf16* __restrict__ hi,
                             bf16* __restrict__ lo, int n4)
{
    int i = blockIdx.x * 256 + threadIdx.x;
    if (i >= n4) return;
    float4 v = in[i];
    bf16 h0, l0, h1, l1, h2, l2, h3, l3;
    split_f32(v.x, h0, l0); split_f32(v.y, h1, l1);
    split_f32(v.z, h2, l2); split_f32(v.w, h3, l3);
    long o = (long)i * 4;
    hi[o] = h0; hi[o+1] = h1; hi[o+2] = h2; hi[o+3] = h3;
    lo[o] = l0; lo[o+1] = l1; lo[o+2] = l2; lo[o+3] = l3;
}

// ---------------- bf16 x3 compensated tensor-core GEMM, cp.async 2-stage ----------------
// C = A*B, A/B pre-split (hi,lo) bf16. A: M x K row-major (lda).
// B: K x N (ldb) if !TRANSB, else stored N x K (ldb).
// Requires: M % 128 == 0, N % BN == 0, K % 32 == 0.
// causal: skip tiles with blockIdx.x > blockIdx.y (upper triangle, BN==BM).
// trik:   clamp K to (blockIdx.y+1)*BM (probs beyond causal bound are exactly 0).
#define BM 128
#define BKK 32
#define APITCH 40

template <bool TRANSB, int ACT, bool SPLITOUT, int BN>
__global__ __launch_bounds__(256) void gemm_bf3(
    const bf16* __restrict__ Ah, const bf16* __restrict__ Al, int lda, long sA1, long sA2,
    const bf16* __restrict__ Bh, const bf16* __restrict__ Bl, int ldb, long sB1, long sB2,
    const float* __restrict__ bias, const float* resid,
    float* Cf, bf16* Chi, bf16* Clo, int ldc, long sC1, long sC2,
    int N, int K, int z2count, int causal, int trik)
{
    if (causal && blockIdx.x > blockIdx.y) return;
    if (trik) {
        int kl = (blockIdx.y + 1) * BM;
        if (kl < K) K = kl;
    }

    constexpr int BROWS  = TRANSB ? BN : BKK;
    constexpr int BPITCH = TRANSB ? APITCH : (BN + 8);
    constexpr int ASZ    = BM * APITCH;           // halves per A array per stage
    constexpr int BSZ    = BROWS * BPITCH;        // halves per B array per stage
    constexpr int STAGE  = 2 * ASZ + 2 * BSZ;     // halves per stage
    constexpr int NJ     = BN / 32;               // 16-wide j tiles per warp
    constexpr int EPP    = BN + 4;                // epilogue fp32 pitch

    extern __shared__ __align__(16) char smem_raw[];
    bf16* smem = (bf16*)smem_raw;
    float* Cs = (float*)smem_raw;

    int zb = blockIdx.z / z2count, zh = blockIdx.z % z2count;
    Ah += (long)zb * sA1 + (long)zh * sA2;
    Al += (long)zb * sA1 + (long)zh * sA2;
    Bh += (long)zb * sB1 + (long)zh * sB2;
    Bl += (long)zb * sB1 + (long)zh * sB2;
    long cofs = (long)zb * sC1 + (long)zh * sC2;

    const int by = blockIdx.y * BM;
    const int bx = blockIdx.x * BN;
    const int tid = threadIdx.x;
    const int wid = tid >> 5;
    const int wm = wid & 3;     // 4 row groups of 32
    const int wn = wid >> 2;    // 2 col groups of BN/2

    wmma::fragment<wmma::accumulator, 16, 16, 16, float> acc[2][NJ];
    #pragma unroll
    for (int i = 0; i < 2; i++)
        #pragma unroll
        for (int j = 0; j < NJ; j++)
            wmma::fill_fragment(acc[i][j], 0.0f);

    // ---- async stage loader: copies 32-K chunk k0 into stage stg ----
    auto load_stage = [&](int k0, int stg) {
        bf16* sAh = smem + stg * STAGE;
        bf16* sAl = sAh + ASZ;
        bf16* sBh = sAl + ASZ;
        bf16* sBl = sBh + BSZ;
        // A: 128 rows x 32 halves, 2 x 16B per thread per array
        #pragma unroll
        for (int i = 0; i < 2; i++) {
            int idx = tid + i * 256;
            int r = idx >> 2, v = idx & 3;
            long off = (long)(by + r) * lda + k0 + v * 8;
            cp_async16(sAh + r * APITCH + v * 8, Ah + off);
            cp_async16(sAl + r * APITCH + v * 8, Al + off);
        }
        if (!TRANSB) {
            // B: 32 rows x BN halves
            constexpr int VPR = BN / 8;          // 16B vectors per row
            constexpr int ITER = (BKK * VPR) / 256;
            #pragma unroll
            for (int i = 0; i < (ITER > 0 ? ITER : 1); i++) {
                int idx = tid + i * 256;
                int kr = idx / VPR, v = idx % VPR;
                long off = (long)(k0 + kr) * ldb + bx + v * 8;
                cp_async16(sBh + kr * BPITCH + v * 8, Bh + off);
                cp_async16(sBl + kr * BPITCH + v * 8, Bl + off);
            }
        } else {
            // B: BN rows x 32 halves
            #pragma unroll
            for (int i = 0; i < BN / 64; i++) {
                int idx = tid + i * 256;
                int n = idx >> 2, v = idx & 3;
                long off = (long)(bx + n) * ldb + k0 + v * 8;
                cp_async16(sBh + n * BPITCH + v * 8, Bh + off);
                cp_async16(sBl + n * BPITCH + v * 8, Bl + off);
            }
        }
        cp_commit();
    };

    // ---- mma over one staged 32-K chunk ----
    auto do_mma = [&](int stg) {
        bf16* sAh = smem + stg * STAGE;
        bf16* sAl = sAh + ASZ;
        bf16* sBh = sAl + ASZ;
        bf16* sBl = sBh + BSZ;
        #pragma unroll
        for (int ks = 0; ks < 2; ks++) {
            wmma::fragment<wmma::matrix_a, 16, 16, 16, bf16, wmma::row_major> fah[2], fal[2];
            #pragma unroll
            for (int i = 0; i < 2; i++) {
                int m0 = wm * 32 + i * 16;
                wmma::load_matrix_sync(fah[i], sAh + m0 * APITCH + ks * 16, APITCH);
                wmma::load_matrix_sync(fal[i], sAl + m0 * APITCH + ks * 16, APITCH);
            }
            if (!TRANSB) {
                wmma::fragment<wmma::matrix_b, 16, 16, 16, bf16, wmma::row_major> fbh, fbl;
                #pragma unroll
                for (int j = 0; j < NJ; j++) {
                    int n0 = wn * (BN / 2) + j * 16;
                    wmma::load_matrix_sync(fbh, sBh + ks * 16 * BPITCH + n0, BPITCH);
                    wmma::load_matrix_sync(fbl, sBl + ks * 16 * BPITCH + n0, BPITCH);
                    #pragma unroll
                    for (int i = 0; i < 2; i++) {
                        wmma::mma_sync(acc[i][j], fah[i], fbl, acc[i][j]);
                        wmma::mma_sync(acc[i][j], fal[i], fbh, acc[i][j]);
                        wmma::mma_sync(acc[i][j], fah[i], fbh, acc[i][j]);
                    }
                }
            } else {
                wmma::fragment<wmma::matrix_b, 16, 16, 16, bf16, wmma::col_major> fbh, fbl;
                #pragma unroll
                for (int j = 0; j < NJ; j++) {
                    int n0 = wn * (BN / 2) + j * 16;
                    wmma::load_matrix_sync(fbh, sBh + n0 * BPITCH + ks * 16, BPITCH);
                    wmma::load_matrix_sync(fbl, sBl + n0 * BPITCH + ks * 16, BPITCH);
                    #pragma unroll
                    for (int i = 0; i < 2; i++) {
                        wmma::mma_sync(acc[i][j], fah[i], fbl, acc[i][j]);
                        wmma::mma_sync(acc[i][j], fal[i], fbh, acc[i][j]);
                        wmma::mma_sync(acc[i][j], fah[i], fbh, acc[i][j]);
                    }
                }
            }
        }
    };

    const int nk = K / BKK;
    load_stage(0, 0);
    if (nk > 1) load_stage(BKK, 1); else cp_commit();

    for (int i = 0; i < nk; i++) {
        if (i < nk - 1) cp_wait<1>(); else cp_wait<0>();
        __syncthreads();
        do_mma(i & 1);
        __syncthreads();
        if (i + 2 < nk) load_stage((i + 2) * BKK, i & 1);
    }

    // ---- epilogue: two 64-row waves through 64 x EPP fp32 staging ----
    #pragma unroll
    for (int wave = 0; wave < 2; wave++) {
        if ((wm >> 1) == wave) {
            int rbase = (wm & 1) * 32;
            #pragma unroll
            for (int i = 0; i < 2; i++)
                #pragma unroll
                for (int j = 0; j < NJ; j++)
                    wmma::store_matrix_sync(Cs + (rbase + i * 16) * EPP + wn * (BN / 2) + j * 16,
                                            acc[i][j], EPP, wmma::mem_row_major);
        }
        __syncthreads();
        constexpr int EITER = (64 * BN) / 256;
        #pragma unroll 4
        for (int e = 0; e < EITER; e++) {
            int idx = tid + e * 256;
            int r = idx / BN, n = idx % BN;
            int gn = bx + n;
            float v = Cs[r * EPP + n];
            if (bias) v += bias[gn];
            long off = cofs + (long)(by + wave * 64 + r) * ldc + gn;
            if (ACT == 1) v = 0.5f * v * (1.0f + erff(v * 0.70710678118654752f));
            if (SPLITOUT) {
                bf16 h, l; split_f32(v, h, l);
                Chi[off] = h; Clo[off] = l;
            } else {
                if (resid) v += resid[off];
                Cf[off] = v;
            }
        }
        __syncthreads();
    }
}

// host-side smem size mirror
static inline int gemm_smem_bytes(bool transb, int bn) {
    int bsz = transb ? bn * APITCH : BKK * (bn + 8);
    int stage = 2 * BM * APITCH + 2 * bsz;
    return 2 * stage * 2;   // 2 stages, bf16
}

// ---------------- layernorm -> split bf16 ----------------
__global__ void ln_split_kernel(const float* __restrict__ x, const float* __restrict__ w,
                                const float* __restrict__ b, bf16* __restrict__ oh,
                                bf16* __restrict__ ol)
{
    int row = blockIdx.x;
    const float* xr = x + (long)row * CDIM;
    int tid = threadIdx.x;  // 256
    float v[3];
    float s = 0.f, s2 = 0.f;
    #pragma unroll
    for (int i = 0; i < 3; i++) {
        int c = tid + i * 256;
        float t = xr[c];
        v[i] = t; s += t; s2 += t * t;
    }
    __shared__ float r1[256], r2[256];
    r1[tid] = s; r2[tid] = s2;
    __syncthreads();
    for (int st = 128; st > 0; st >>= 1) {
        if (tid < st) { r1[tid] += r1[tid + st]; r2[tid] += r2[tid + st]; }
        __syncthreads();
    }
    float mean = r1[0] * (1.0f / CDIM);
    float var  = r2[0] * (1.0f / CDIM) - mean * mean;
    float rstd = rsqrtf(var + 1e-5f);
    #pragma unroll
    for (int i = 0; i < 3; i++) {
        int c = tid + i * 256;
        float o = (v[i] - mean) * rstd * w[c] + b[c];
        bf16 h, l; split_f32(o, h, l);
        oh[(long)row * CDIM + c] = h;
        ol[(long)row * CDIM + c] = l;
    }
}

// ---------------- embedding / init ----------------
__global__ void embed_kernel(const int* __restrict__ idx, const float* __restrict__ wte,
                             const float* __restrict__ wpe, float* __restrict__ x)
{
    int row = blockIdx.x;
    int t = row % TSEQ;
    int tok = idx[row];
    const float* we = wte + (long)tok * CDIM;
    const float* wp = wpe + (long)t * CDIM;
    float* xr = x + (long)row * CDIM;
    for (int c = threadIdx.x; c < CDIM; c += 256)
        xr[c] = we[c] + wp[c];
}

__global__ void init_am_kernel(float* am)
{
    int i = blockIdx.x * 256 + threadIdx.x;
    if (i < NTOK) am[i] = 1.0f;
}

__global__ void zero_kernel(float* p, int n)
{
    int i = blockIdx.x * 256 + threadIdx.x;
    if (i < n) p[i] = 0.0f;
}

// ---------------- softmax (+scale+causal+key-mask) -> split bf16 probs ----------------
// Causal traffic skip: row q only touches k < klim = (q/128+1)*128. Beyond klim the
// score tiles were never written (causal tile skip) and att is never read
// (att@V trik clamp + causal imp_reduce), so we neither read nor write there.
__global__ void softmax_mask_kernel(const float* __restrict__ score, const float* __restrict__ am,
                                    bf16* __restrict__ ah, bf16* __restrict__ al)
{
    long z = blockIdx.x;             // (b*H + h)*T + q
    int q = (int)(z % TSEQ);
    int b = (int)(z / ((long)NHEAD * TSEQ));
    const float* row = score + z * TSEQ;
    const float* amr = am + (long)b * TSEQ;
    int tid = threadIdx.x;  // 256
    const int klim = ((q >> 7) + 1) << 7;

    float vals[4];
    float lmax = -CUDART_INF_F;
    #pragma unroll
    for (int i = 0; i < 4; i++) {
        int k = tid + i * 256;
        float sc = -CUDART_INF_F;
        if (k < klim) {
            float raw = row[k] * 0.125f;
            bool valid = (k <= q) && (amr[k] > 0.0f);
            sc = valid ? raw : -CUDART_INF_F;
        }
        vals[i] = sc;
        lmax = fmaxf(lmax, sc);
    }
    __shared__ float red[256];
    red[tid] = lmax;
    __syncthreads();
    for (int st = 128; st > 0; st >>= 1) {
        if (tid < st) red[tid] = fmaxf(red[tid], red[tid + st]);
        __syncthreads();
    }
    float m = red[0];
    __syncthreads();
    float lsum = 0.f;
    #pragma unroll
    for (int i = 0; i < 4; i++) {
        float e = expf(vals[i] - m);
        vals[i] = e;
        lsum += e;
    }
    red[tid] = lsum;
    __syncthreads();
    for (int st = 128; st > 0; st >>= 1) {
        if (tid < st) red[tid] += red[tid + st];
        __syncthreads();
    }
    float inv = 1.0f / red[0];
    #pragma unroll
    for (int i = 0; i < 4; i++) {
        int k = tid + i * 256;
        if (k < klim) {
            float p = vals[i] * inv;
            bf16 h, l; split_f32(p, h, l);
            ah[z * TSEQ + k] = h;
            al[z * TSEQ + k] = l;
        }
    }
}

// ---------------- importance reduce (causal: rows q < (k/128)*128 were never written) ----------------
__global__ void imp_reduce_kernel(const bf16* __restrict__ ah, const bf16* __restrict__ al,
                                  float* __restrict__ imp)
{
    int b = blockIdx.x;
    int k = blockIdx.y * 256 + threadIdx.x;
    int q0 = blockIdx.z * (TSEQ / 16);   // 64 queries per block
    int kt = (k >> 7) << 7;              // first q with valid att[q][k]
    int qs = q0 > kt ? q0 : kt;
    int qe = q0 + TSEQ / 16;
    float s = 0.f;
    if (qs < qe) {
        for (int h = 0; h < NHEAD; h++) {
            long base = ((long)(b * NHEAD + h) * TSEQ) * TSEQ + k;
            #pragma unroll 4
            for (int q = qs; q < qe; q++) {
                long o = base + (long)q * TSEQ;
                s += __bfloat162float(ah[o]) + __bfloat162float(al[o]);
            }
        }
    }
    atomicAdd(&imp[b * TSEQ + k], s);
}

// ---------------- pruning mask update / apply ----------------
__global__ void prune_mask_kernel(const float* __restrict__ imp, float* __restrict__ am,
                                  const float* __restrict__ thresholds, int layer)
{
    int i = blockIdx.x * 256 + threadIdx.x;
    if (i >= NTOK) return;
    int t = i % TSEQ;
    float th = thresholds[layer];
    float v = imp[i] * (1.0f / ((float)NHEAD * (float)TSEQ));
    float pm = (t >= TSEQ - MINKEEP) ? 1.0f : ((v >= th) ? 1.0f : 0.0f);  // NaN>=th -> false
    am[i] = am[i] * pm;
}

__global__ void scale_rows_kernel(float* __restrict__ x, const float* __restrict__ am)
{
    int row = blockIdx.x;
    float s = am[row];
    float* xr = x + (long)row * CDIM;
    for (int c = threadIdx.x; c < CDIM; c += 256)
        xr[c] *= s;
}

// ---------------- loss ----------------
__global__ void loss_row_kernel(const float* __restrict__ logits, const int* __restrict__ targets,
                                float* __restrict__ nll)
{
    int row = blockIdx.x;
    const float* lr = logits + (long)row * VOCAB;
    int tid = threadIdx.x;  // 256
    float m = -CUDART_INF_F;
    for (int c = tid; c < VOCAB; c += 256) m = fmaxf(m, lr[c]);
    __shared__ float red[256];
    red[tid] = m;
    __syncthreads();
    for (int st = 128; st > 0; st >>= 1) {
        if (tid < st) red[tid] = fmaxf(red[tid], red[tid + st]);
        __syncthreads();
    }
    m = red[0];
    __syncthreads();
    float s = 0.f;
    for (int c = tid; c < VOCAB; c += 256) s += expf(lr[c] - m);
    red[tid] = s;
    __syncthreads();
    for (int st = 128; st > 0; st >>= 1) {
        if (tid < st) red[tid] += red[tid + st];
        __syncthreads();
    }
    if (tid == 0) {
        int tgt = targets[row];
        float v = 0.f;
        if (tgt != -1) v = m + logf(red[0]) - lr[tgt];
        nll[row] = v;
    }
}

__global__ void loss_final_kernel(const float* __restrict__ nll, const int* __restrict__ targets,
                                  float* __restrict__ out)
{
    int tid = threadIdx.x;  // 256
    float s = 0.f, cnt = 0.f;
    for (int i = tid; i < NTOK; i += 256) {
        if (targets[i] != -1) { s += nll[i]; cnt += 1.f; }
    }
    __shared__ float r1[256], r2[256];
    r1[tid] = s; r2[tid] = cnt;
    __syncthreads();
    for (int st = 128; st > 0; st >>= 1) {
        if (tid < st) { r1[tid] += r1[tid + st]; r2[tid] += r2[tid + st]; }
        __syncthreads();
    }
    if (tid == 0) out[0] = r1[0] / r2[0];
}

// ---------------- host orchestration ----------------
extern "C" void kernel_launch(void* const* d_in, const int* in_sizes, int n_in,
                              void* d_out, int out_size)
{
    const int*   idx        = (const int*)d_in[0];
    const int*   targets    = (const int*)d_in[1];
    const float* wte        = (const float*)d_in[2];
    const float* wpe        = (const float*)d_in[3];
    const float* ln1_w      = (const float*)d_in[4];
    const float* ln1_b      = (const float*)d_in[5];
    const float* attn_w     = (const float*)d_in[6];
    const float* attn_b     = (const float*)d_in[7];
    const float* proj_w     = (const float*)d_in[8];
    const float* proj_b     = (const float*)d_in[9];
    const float* ln2_w      = (const float*)d_in[10];
    const float* ln2_b      = (const float*)d_in[11];
    const float* fc_w       = (const float*)d_in[12];
    const float* fc_b       = (const float*)d_in[13];
    const float* mlp_w      = (const float*)d_in[14];
    const float* mlp_b      = (const float*)d_in[15];
    const float* thresholds = (const float*)d_in[16];
    const float* lnf_w      = (const float*)d_in[17];
    const float* lnf_b      = (const float*)d_in[18];

    float *x, *score, *am, *imp, *nll;
    bf16 *hh, *hl, *qh, *ql, *atth, *attl, *yh, *yl, *fch, *fcl;
    bf16 *awh, *awl, *pwh, *pwl, *fwh, *fwl, *mwh, *mwl, *wteh, *wtel;
    cudaGetSymbolAddress((void**)&x,     g_x);
    cudaGetSymbolAddress((void**)&score, g_score);
    cudaGetSymbolAddress((void**)&am,    g_am);
    cudaGetSymbolAddress((void**)&imp,   g_imp);
    cudaGetSymbolAddress((void**)&nll,   g_nll);
    cudaGetSymbolAddress((void**)&hh,    g_h_hi);   cudaGetSymbolAddress((void**)&hl, g_h_lo);
    cudaGetSymbolAddress((void**)&qh,    g_qkv_hi); cudaGetSymbolAddress((void**)&ql, g_qkv_lo);
    cudaGetSymbolAddress((void**)&atth,  g_att_hi); cudaGetSymbolAddress((void**)&attl, g_att_lo);
    cudaGetSymbolAddress((void**)&yh,    g_y_hi);   cudaGetSymbolAddress((void**)&yl, g_y_lo);
    cudaGetSymbolAddress((void**)&fch,   g_fc_hi);  cudaGetSymbolAddress((void**)&fcl, g_fc_lo);
    cudaGetSymbolAddress((void**)&awh,   g_aw_hi);  cudaGetSymbolAddress((void**)&awl, g_aw_lo);
    cudaGetSymbolAddress((void**)&pwh,   g_pw_hi);  cudaGetSymbolAddress((void**)&pwl, g_pw_lo);
    cudaGetSymbolAddress((void**)&fwh,   g_fw_hi);  cudaGetSymbolAddress((void**)&fwl, g_fw_lo);
    cudaGetSymbolAddress((void**)&mwh,   g_mw_hi);  cudaGetSymbolAddress((void**)&mwl, g_mw_lo);
    cudaGetSymbolAddress((void**)&wteh,  g_wte_hi); cudaGetSymbolAddress((void**)&wtel, g_wte_lo);

    float* out = (float*)d_out;

    const int SM_NT  = gemm_smem_bytes(false, 128);  // 75776
    const int SM_T   = gemm_smem_bytes(true, 128);   // 81920
    const int SM_N64 = gemm_smem_bytes(false, 64);   // 59392

    static bool attr_done = false;
    if (!attr_done) {
        cudaFuncSetAttribute(gemm_bf3<false, 0, true, 128>, cudaFuncAttributeMaxDynamicSharedMemorySize, SM_NT);
        cudaFuncSetAttribute(gemm_bf3<false, 1, true, 128>, cudaFuncAttributeMaxDynamicSharedMemorySize, SM_NT);
        cudaFuncSetAttribute(gemm_bf3<false, 0, false, 128>, cudaFuncAttributeMaxDynamicSharedMemorySize, SM_NT);
        cudaFuncSetAttribute(gemm_bf3<true, 0, false, 128>, cudaFuncAttributeMaxDynamicSharedMemorySize, SM_T);
        cudaFuncSetAttribute(gemm_bf3<false, 0, true, 64>, cudaFuncAttributeMaxDynamicSharedMemorySize, SM_N64);
        attr_done = true;
    }

    // split all weights
    {
        int n;
        n = NLAYER * CDIM * C3 / 4;
        split_kernel<<<(n + 255) / 256, 256>>>((const float4*)attn_w, awh, awl, n);
        n = NLAYER * CDIM * CDIM / 4;
        split_kernel<<<(n + 255) / 256, 256>>>((const float4*)proj_w, pwh, pwl, n);
        n = NLAYER * CDIM * C4 / 4;
        split_kernel<<<(n + 255) / 256, 256>>>((const float4*)fc_w, fwh, fwl, n);
        n = NLAYER * C4 * CDIM / 4;
        split_kernel<<<(n + 255) / 256, 256>>>((const float4*)mlp_w, mwh, mwl, n);
        n = VOCAB * CDIM / 4;
        split_kernel<<<(n + 255) / 256, 256>>>((const float4*)wte, wteh, wtel, n);
    }

    embed_kernel<<<NTOK, 256>>>(idx, wte, wpe, x);
    init_am_kernel<<<NTOK / 256, 256>>>(am);

    for (int l = 0; l < NLAYER; l++) {
        ln_split_kernel<<<NTOK, 256>>>(x, ln1_w + (long)l * CDIM, ln1_b + (long)l * CDIM, hh, hl);

        // qkv = h @ attn_w + attn_b -> split out
        gemm_bf3<false, 0, true, 128><<<dim3(C3 / 128, NTOK / BM, 1), 256, SM_NT>>>(
            hh, hl, CDIM, 0, 0,
            awh + (long)l * CDIM * C3, awl + (long)l * CDIM * C3, C3, 0, 0,
            attn_b + (long)l * C3, nullptr,
            nullptr, qh, ql, C3, 0, 0, C3, CDIM, 1, 0, 0);

        // scores = Q K^T (fp32), batched over b*H — causal tile skip
        gemm_bf3<true, 0, false, 128><<<dim3(TSEQ / 128, TSEQ / BM, BBATCH * NHEAD), 256, SM_T>>>(
            qh, ql, C3, (long)TSEQ * C3, HSZ,
            qh + CDIM, ql + CDIM, C3, (long)TSEQ * C3, HSZ,
            nullptr, nullptr,
            score, nullptr, nullptr, TSEQ, (long)NHEAD * TSEQ * TSEQ, (long)TSEQ * TSEQ,
            TSEQ, HSZ, NHEAD, 1, 0);

        softmax_mask_kernel<<<BBATCH * NHEAD * TSEQ, 256>>>(score, am, atth, attl);

        zero_kernel<<<NTOK / 256, 256>>>(imp, NTOK);
        imp_reduce_kernel<<<dim3(BBATCH, TSEQ / 256, 16), 256>>>(atth, attl, imp);

        // y = att @ V -> split out (BN=64; triangular K clamp — probs beyond are exactly 0)
        gemm_bf3<false, 0, true, 64><<<dim3(1, TSEQ / BM, BBATCH * NHEAD), 256, SM_N64>>>(
            atth, attl, TSEQ, (long)NHEAD * TSEQ * TSEQ, (long)TSEQ * TSEQ,
            qh + 2 * CDIM, ql + 2 * CDIM, C3, (long)TSEQ * C3, HSZ,
            nullptr, nullptr,
            nullptr, yh, yl, CDIM, (long)TSEQ * CDIM, HSZ,
            HSZ, TSEQ, NHEAD, 0, 1);

        // x = x + y @ proj_w + proj_b (fp32)
        gemm_bf3<false, 0, false, 128><<<dim3(CDIM / 128, NTOK / BM, 1), 256, SM_NT>>>(
            yh, yl, CDIM, 0, 0,
            pwh + (long)l * CDIM * CDIM, pwl + (long)l * CDIM * CDIM, CDIM, 0, 0,
            proj_b + (long)l * CDIM, x,
            x, nullptr, nullptr, CDIM, 0, 0, CDIM, CDIM, 1, 0, 0);

        prune_mask_kernel<<<NTOK / 256, 256>>>(imp, am, thresholds, l);
        scale_rows_kernel<<<NTOK, 256>>>(x, am);

        ln_split_kernel<<<NTOK, 256>>>(x, ln2_w + (long)l * CDIM, ln2_b + (long)l * CDIM, hh, hl);

        // fc = gelu(h @ fc_w + fc_b) -> split out
        gemm_bf3<false, 1, true, 128><<<dim3(C4 / 128, NTOK / BM, 1), 256, SM_NT>>>(
            hh, hl, CDIM, 0, 0,
            fwh + (long)l * CDIM * C4, fwl + (long)l * CDIM * C4, C4, 0, 0,
            fc_b + (long)l * C4, nullptr,
            nullptr, fch, fcl, C4, 0, 0, C4, CDIM, 1, 0, 0);

        // x = x + fc @ mlp_w + mlp_b (fp32)
        gemm_bf3<false, 0, false, 128><<<dim3(CDIM / 128, NTOK / BM, 1), 256, SM_NT>>>(
            fch, fcl, C4, 0, 0,
            mwh + (long)l * C4 * CDIM, mwl + (long)l * C4 * CDIM, CDIM, 0, 0,
            mlp_b + (long)l * CDIM, x,
            x, nullptr, nullptr, CDIM, 0, 0, CDIM, C4, 1, 0, 0);
    }

    ln_split_kernel<<<NTOK, 256>>>(x, lnf_w, lnf_b, hh, hl);

    // logits = h @ wte^T (fp32 out)  — VOCAB = 50304 = 393 * 128, exact
    gemm_bf3<true, 0, false, 128><<<dim3(VOCAB / 128, NTOK / BM, 1), 256, SM_T>>>(
        hh, hl, CDIM, 0, 0,
        wteh, wtel, CDIM, 0, 0,
        nullptr, nullptr,
        out, nullptr, nullptr, VOCAB, 0, 0, VOCAB, CDIM, 1, 0, 0);

    loss_row_kernel<<<NTOK, 256>>>(out, targets, nll);
    if ((long)out_size >= (long)NTOK * VOCAB + 1)
        loss_final_kernel<<<1, 256>>>(nll, targets, out + (long)NTOK * VOCAB);
}

// round 16
// speedup vs baseline: 1.5817x; 1.0532x over previous
#include <cuda_runtime.h>
#include <cuda_bf16.h>
#include <cstdint>
#include <math.h>
#include <math_constants.h>
#include <mma.h>

using namespace nvcuda;

#define NLAYER 12
#define NHEAD  12
#define CDIM   768
#define HSZ    64
#define VOCAB  50304
#define BBATCH 2
#define TSEQ   1024
#define NTOK   (BBATCH * TSEQ)
#define C3     (3 * CDIM)
#define C4     (4 * CDIM)
#define MINKEEP 64

typedef __nv_bfloat16 bf16;

// ---------------- static device scratch ----------------
__device__ float g_x[NTOK * CDIM];
__device__ float g_score[(long)BBATCH * NHEAD * TSEQ * TSEQ];
__device__ bf16  g_h_hi[NTOK * CDIM],  g_h_lo[NTOK * CDIM];
__device__ bf16  g_qkv_hi[NTOK * C3],  g_qkv_lo[NTOK * C3];
__device__ bf16  g_att_hi[(long)BBATCH * NHEAD * TSEQ * TSEQ];
__device__ bf16  g_att_lo[(long)BBATCH * NHEAD * TSEQ * TSEQ];
__device__ bf16  g_y_hi[NTOK * CDIM],  g_y_lo[NTOK * CDIM];
__device__ bf16  g_fc_hi[NTOK * C4],   g_fc_lo[NTOK * C4];
__device__ bf16  g_aw_hi[NLAYER * CDIM * C3],   g_aw_lo[NLAYER * CDIM * C3];
__device__ bf16  g_pw_hi[NLAYER * CDIM * CDIM], g_pw_lo[NLAYER * CDIM * CDIM];
__device__ bf16  g_fw_hi[NLAYER * CDIM * C4],   g_fw_lo[NLAYER * CDIM * C4];
__device__ bf16  g_mw_hi[NLAYER * C4 * CDIM],   g_mw_lo[NLAYER * C4 * CDIM];
__device__ bf16  g_wte_hi[VOCAB * CDIM],        g_wte_lo[VOCAB * CDIM];
__device__ float g_am[NTOK];
__device__ float g_imp[NTOK];
__device__ float g_nll[NTOK];

__device__ __forceinline__ void split_f32(float v, bf16& h, bf16& l) {
    h = __float2bfloat16_rn(v);
    l = __float2bfloat16_rn(v - __bfloat162float(h));
}

// ---------------- cp.async helpers ----------------
__device__ __forceinline__ void cp_async16(void* d, const void* s) {
    asm volatile("cp.async.cg.shared.global [%0], [%1], 16;" ::
        "r"((unsigned)__cvta_generic_to_shared(d)), "l"(s));
}
__device__ __forceinline__ void cp_commit() { asm volatile("cp.async.commit_group;"); }
template<int N> __device__ __forceinline__ void cp_wait() {
    asm volatile("cp.async.wait_group %0;" :: "n"(N));
}

// ---------------- weight split: fp32 -> (hi, lo) bf16 ----------------
__global__ void split_kernel(const float4* __restrict__ in, bf16* __restrict__ hi,
                             bf16* __restrict__ lo, int n4)
{
    int i = blockIdx.x * 256 + threadIdx.x;
    if (i >= n4) return;
    float4 v = in[i];
    bf16 h0, l0, h1, l1, h2, l2, h3, l3;
    split_f32(v.x, h0, l0); split_f32(v.y, h1, l1);
    split_f32(v.z, h2, l2); split_f32(v.w, h3, l3);
    long o = (long)i * 4;
    hi[o] = h0; hi[o+1] = h1; hi[o+2] = h2; hi[o+3] = h3;
    lo[o] = l0; lo[o+1] = l1; lo[o+2] = l2; lo[o+3] = l3;
}

// ---------------- bf16 x3 compensated tensor-core GEMM, cp.async 2-stage ----------------
// C = A*B, A/B pre-split (hi,lo) bf16. A: M x K row-major (lda).
// B: K x N (ldb) if !TRANSB, else stored N x K (ldb).
// Requires: M % 128 == 0, N % BN == 0, K % 32 == 0.
// causal: skip tiles with blockIdx.x > blockIdx.y (upper triangle, BN==BM).
// trik:   clamp K to (blockIdx.y+1)*BM (probs beyond causal bound are exactly 0).
#define BM 128
#define BKK 32
#define APITCH 40

template <bool TRANSB, int ACT, bool SPLITOUT, int BN>
__global__ __launch_bounds__(256, 2) void gemm_bf3(
    const bf16* __restrict__ Ah, const bf16* __restrict__ Al, int lda, long sA1, long sA2,
    const bf16* __restrict__ Bh, const bf16* __restrict__ Bl, int ldb, long sB1, long sB2,
    const float* __restrict__ bias, const float* resid,
    float* Cf, bf16* Chi, bf16* Clo, int ldc, long sC1, long sC2,
    int N, int K, int z2count, int causal, int trik)
{
    if (causal && blockIdx.x > blockIdx.y) return;
    if (trik) {
        int kl = (blockIdx.y + 1) * BM;
        if (kl < K) K = kl;
    }

    constexpr int BROWS  = TRANSB ? BN : BKK;
    constexpr int BPITCH = TRANSB ? APITCH : (BN + 8);
    constexpr int ASZ    = BM * APITCH;
    constexpr int BSZ    = BROWS * BPITCH;
    constexpr int STAGE  = 2 * ASZ + 2 * BSZ;
    constexpr int NJ     = BN / 32;
    constexpr int EPP    = BN + 4;

    extern __shared__ __align__(16) char smem_raw[];
    bf16* smem = (bf16*)smem_raw;
    float* Cs = (float*)smem_raw;

    int zb = blockIdx.z / z2count, zh = blockIdx.z % z2count;
    Ah += (long)zb * sA1 + (long)zh * sA2;
    Al += (long)zb * sA1 + (long)zh * sA2;
    Bh += (long)zb * sB1 + (long)zh * sB2;
    Bl += (long)zb * sB1 + (long)zh * sB2;
    long cofs = (long)zb * sC1 + (long)zh * sC2;

    const int by = blockIdx.y * BM;
    const int bx = blockIdx.x * BN;
    const int tid = threadIdx.x;
    const int wid = tid >> 5;
    const int wm = wid & 3;
    const int wn = wid >> 2;

    wmma::fragment<wmma::accumulator, 16, 16, 16, float> acc[2][NJ];
    #pragma unroll
    for (int i = 0; i < 2; i++)
        #pragma unroll
        for (int j = 0; j < NJ; j++)
            wmma::fill_fragment(acc[i][j], 0.0f);

    auto load_stage = [&](int k0, int stg) {
        bf16* sAh = smem + stg * STAGE;
        bf16* sAl = sAh + ASZ;
        bf16* sBh = sAl + ASZ;
        bf16* sBl = sBh + BSZ;
        #pragma unroll
        for (int i = 0; i < 2; i++) {
            int idx = tid + i * 256;
            int r = idx >> 2, v = idx & 3;
            long off = (long)(by + r) * lda + k0 + v * 8;
            cp_async16(sAh + r * APITCH + v * 8, Ah + off);
            cp_async16(sAl + r * APITCH + v * 8, Al + off);
        }
        if (!TRANSB) {
            constexpr int VPR = BN / 8;
            constexpr int ITER = (BKK * VPR) / 256;
            #pragma unroll
            for (int i = 0; i < (ITER > 0 ? ITER : 1); i++) {
                int idx = tid + i * 256;
                int kr = idx / VPR, v = idx % VPR;
                long off = (long)(k0 + kr) * ldb + bx + v * 8;
                cp_async16(sBh + kr * BPITCH + v * 8, Bh + off);
                cp_async16(sBl + kr * BPITCH + v * 8, Bl + off);
            }
        } else {
            #pragma unroll
            for (int i = 0; i < BN / 64; i++) {
                int idx = tid + i * 256;
                int n = idx >> 2, v = idx & 3;
                long off = (long)(bx + n) * ldb + k0 + v * 8;
                cp_async16(sBh + n * BPITCH + v * 8, Bh + off);
                cp_async16(sBl + n * BPITCH + v * 8, Bl + off);
            }
        }
        cp_commit();
    };

    auto do_mma = [&](int stg) {
        bf16* sAh = smem + stg * STAGE;
        bf16* sAl = sAh + ASZ;
        bf16* sBh = sAl + ASZ;
        bf16* sBl = sBh + BSZ;
        #pragma unroll
        for (int ks = 0; ks < 2; ks++) {
            wmma::fragment<wmma::matrix_a, 16, 16, 16, bf16, wmma::row_major> fah[2], fal[2];
            #pragma unroll
            for (int i = 0; i < 2; i++) {
                int m0 = wm * 32 + i * 16;
                wmma::load_matrix_sync(fah[i], sAh + m0 * APITCH + ks * 16, APITCH);
                wmma::load_matrix_sync(fal[i], sAl + m0 * APITCH + ks * 16, APITCH);
            }
            if (!TRANSB) {
                wmma::fragment<wmma::matrix_b, 16, 16, 16, bf16, wmma::row_major> fbh, fbl;
                #pragma unroll
                for (int j = 0; j < NJ; j++) {
                    int n0 = wn * (BN / 2) + j * 16;
                    wmma::load_matrix_sync(fbh, sBh + ks * 16 * BPITCH + n0, BPITCH);
                    wmma::load_matrix_sync(fbl, sBl + ks * 16 * BPITCH + n0, BPITCH);
                    #pragma unroll
                    for (int i = 0; i < 2; i++) {
                        wmma::mma_sync(acc[i][j], fah[i], fbl, acc[i][j]);
                        wmma::mma_sync(acc[i][j], fal[i], fbh, acc[i][j]);
                        wmma::mma_sync(acc[i][j], fah[i], fbh, acc[i][j]);
                    }
                }
            } else {
                wmma::fragment<wmma::matrix_b, 16, 16, 16, bf16, wmma::col_major> fbh, fbl;
                #pragma unroll
                for (int j = 0; j < NJ; j++) {
                    int n0 = wn * (BN / 2) + j * 16;
                    wmma::load_matrix_sync(fbh, sBh + n0 * BPITCH + ks * 16, BPITCH);
                    wmma::load_matrix_sync(fbl, sBl + n0 * BPITCH + ks * 16, BPITCH);
                    #pragma unroll
                    for (int i = 0; i < 2; i++) {
                        wmma::mma_sync(acc[i][j], fah[i], fbl, acc[i][j]);
                        wmma::mma_sync(acc[i][j], fal[i], fbh, acc[i][j]);
                        wmma::mma_sync(acc[i][j], fah[i], fbh, acc[i][j]);
                    }
                }
            }
        }
    };

    const int nk = K / BKK;
    load_stage(0, 0);
    if (nk > 1) load_stage(BKK, 1); else cp_commit();

    for (int i = 0; i < nk; i++) {
        if (i < nk - 1) cp_wait<1>(); else cp_wait<0>();
        __syncthreads();
        do_mma(i & 1);
        __syncthreads();
        if (i + 2 < nk) load_stage((i + 2) * BKK, i & 1);
    }

    #pragma unroll
    for (int wave = 0; wave < 2; wave++) {
        if ((wm >> 1) == wave) {
            int rbase = (wm & 1) * 32;
            #pragma unroll
            for (int i = 0; i < 2; i++)
                #pragma unroll
                for (int j = 0; j < NJ; j++)
                    wmma::store_matrix_sync(Cs + (rbase + i * 16) * EPP + wn * (BN / 2) + j * 16,
                                            acc[i][j], EPP, wmma::mem_row_major);
        }
        __syncthreads();
        constexpr int EITER = (64 * BN) / 256;
        #pragma unroll 4
        for (int e = 0; e < EITER; e++) {
            int idx = tid + e * 256;
            int r = idx / BN, n = idx % BN;
            int gn = bx + n;
            float v = Cs[r * EPP + n];
            if (bias) v += bias[gn];
            long off = cofs + (long)(by + wave * 64 + r) * ldc + gn;
            if (ACT == 1) v = 0.5f * v * (1.0f + erff(v * 0.70710678118654752f));
            if (SPLITOUT) {
                bf16 h, l; split_f32(v, h, l);
                Chi[off] = h; Clo[off] = l;
            } else {
                if (resid) v += resid[off];
                Cf[off] = v;
            }
        }
        __syncthreads();
    }
}

static inline int gemm_smem_bytes(bool transb, int bn) {
    int bsz = transb ? bn * APITCH : BKK * (bn + 8);
    int stage = 2 * BM * APITCH + 2 * bsz;
    return 2 * stage * 2;
}

// ---------------- layernorm -> split bf16 ----------------
__global__ void ln_split_kernel(const float* __restrict__ x, const float* __restrict__ w,
                                const float* __restrict__ b, bf16* __restrict__ oh,
                                bf16* __restrict__ ol)
{
    int row = blockIdx.x;
    const float* xr = x + (long)row * CDIM;
    int tid = threadIdx.x;
    float v[3];
    float s = 0.f, s2 = 0.f;
    #pragma unroll
    for (int i = 0; i < 3; i++) {
        int c = tid + i * 256;
        float t = xr[c];
        v[i] = t; s += t; s2 += t * t;
    }
    __shared__ float r1[256], r2[256];
    r1[tid] = s; r2[tid] = s2;
    __syncthreads();
    for (int st = 128; st > 0; st >>= 1) {
        if (tid < st) { r1[tid] += r1[tid + st]; r2[tid] += r2[tid + st]; }
        __syncthreads();
    }
    float mean = r1[0] * (1.0f / CDIM);
    float var  = r2[0] * (1.0f / CDIM) - mean * mean;
    float rstd = rsqrtf(var + 1e-5f);
    #pragma unroll
    for (int i = 0; i < 3; i++) {
        int c = tid + i * 256;
        float o = (v[i] - mean) * rstd * w[c] + b[c];
        bf16 h, l; split_f32(o, h, l);
        oh[(long)row * CDIM + c] = h;
        ol[(long)row * CDIM + c] = l;
    }
}

// ---------------- embedding / init ----------------
__global__ void embed_kernel(const int* __restrict__ idx, const float* __restrict__ wte,
                             const float* __restrict__ wpe, float* __restrict__ x)
{
    int row = blockIdx.x;
    int t = row % TSEQ;
    int tok = idx[row];
    const float* we = wte + (long)tok * CDIM;
    const float* wp = wpe + (long)t * CDIM;
    float* xr = x + (long)row * CDIM;
    for (int c = threadIdx.x; c < CDIM; c += 256)
        xr[c] = we[c] + wp[c];
}

__global__ void init_am_kernel(float* am)
{
    int i = blockIdx.x * 256 + threadIdx.x;
    if (i < NTOK) am[i] = 1.0f;
}

__global__ void zero_kernel(float* p, int n)
{
    int i = blockIdx.x * 256 + threadIdx.x;
    if (i < n) p[i] = 0.0f;
}

// ---------------- softmax (+scale+causal+key-mask) -> split bf16 probs ----------------
__global__ void softmax_mask_kernel(const float* __restrict__ score, const float* __restrict__ am,
                                    bf16* __restrict__ ah, bf16* __restrict__ al)
{
    long z = blockIdx.x;
    int q = (int)(z % TSEQ);
    int b = (int)(z / ((long)NHEAD * TSEQ));
    const float* row = score + z * TSEQ;
    const float* amr = am + (long)b * TSEQ;
    int tid = threadIdx.x;
    const int klim = ((q >> 7) + 1) << 7;

    float vals[4];
    float lmax = -CUDART_INF_F;
    #pragma unroll
    for (int i = 0; i < 4; i++) {
        int k = tid + i * 256;
        float sc = -CUDART_INF_F;
        if (k < klim) {
            float raw = row[k] * 0.125f;
            bool valid = (k <= q) && (amr[k] > 0.0f);
            sc = valid ? raw : -CUDART_INF_F;
        }
        vals[i] = sc;
        lmax = fmaxf(lmax, sc);
    }
    __shared__ float red[256];
    red[tid] = lmax;
    __syncthreads();
    for (int st = 128; st > 0; st >>= 1) {
        if (tid < st) red[tid] = fmaxf(red[tid], red[tid + st]);
        __syncthreads();
    }
    float m = red[0];
    __syncthreads();
    float lsum = 0.f;
    #pragma unroll
    for (int i = 0; i < 4; i++) {
        float e = expf(vals[i] - m);
        vals[i] = e;
        lsum += e;
    }
    red[tid] = lsum;
    __syncthreads();
    for (int st = 128; st > 0; st >>= 1) {
        if (tid < st) red[tid] += red[tid + st];
        __syncthreads();
    }
    float inv = 1.0f / red[0];
    #pragma unroll
    for (int i = 0; i < 4; i++) {
        int k = tid + i * 256;
        if (k < klim) {
            float p = vals[i] * inv;
            bf16 h, l; split_f32(p, h, l);
            ah[z * TSEQ + k] = h;
            al[z * TSEQ + k] = l;
        }
    }
}

// ---------------- importance reduce (causal) ----------------
__global__ void imp_reduce_kernel(const bf16* __restrict__ ah, const bf16* __restrict__ al,
                                  float* __restrict__ imp)
{
    int b = blockIdx.x;
    int k = blockIdx.y * 256 + threadIdx.x;
    int q0 = blockIdx.z * (TSEQ / 16);
    int kt = (k >> 7) << 7;
    int qs = q0 > kt ? q0 : kt;
    int qe = q0 + TSEQ / 16;
    float s = 0.f;
    if (qs < qe) {
        for (int h = 0; h < NHEAD; h++) {
            long base = ((long)(b * NHEAD + h) * TSEQ) * TSEQ + k;
            #pragma unroll 4
            for (int q = qs; q < qe; q++) {
                long o = base + (long)q * TSEQ;
                s += __bfloat162float(ah[o]) + __bfloat162float(al[o]);
            }
        }
    }
    atomicAdd(&imp[b * TSEQ + k], s);
}

// ---------------- pruning mask update / apply ----------------
__global__ void prune_mask_kernel(const float* __restrict__ imp, float* __restrict__ am,
                                  const float* __restrict__ thresholds, int layer)
{
    int i = blockIdx.x * 256 + threadIdx.x;
    if (i >= NTOK) return;
    int t = i % TSEQ;
    float th = thresholds[layer];
    float v = imp[i] * (1.0f / ((float)NHEAD * (float)TSEQ));
    float pm = (t >= TSEQ - MINKEEP) ? 1.0f : ((v >= th) ? 1.0f : 0.0f);
    am[i] = am[i] * pm;
}

__global__ void scale_rows_kernel(float* __restrict__ x, const float* __restrict__ am)
{
    int row = blockIdx.x;
    float s = am[row];
    float* xr = x + (long)row * CDIM;
    for (int c = threadIdx.x; c < CDIM; c += 256)
        xr[c] *= s;
}

// ---------------- loss ----------------
__global__ void loss_row_kernel(const float* __restrict__ logits, const int* __restrict__ targets,
                                float* __restrict__ nll)
{
    int row = blockIdx.x;
    const float* lr = logits + (long)row * VOCAB;
    int tid = threadIdx.x;
    float m = -CUDART_INF_F;
    for (int c = tid; c < VOCAB; c += 256) m = fmaxf(m, lr[c]);
    __shared__ float red[256];
    red[tid] = m;
    __syncthreads();
    for (int st = 128; st > 0; st >>= 1) {
        if (tid < st) red[tid] = fmaxf(red[tid], red[tid + st]);
        __syncthreads();
    }
    m = red[0];
    __syncthreads();
    float s = 0.f;
    for (int c = tid; c < VOCAB; c += 256) s += expf(lr[c] - m);
    red[tid] = s;
    __syncthreads();
    for (int st = 128; st > 0; st >>= 1) {
        if (tid < st) red[tid] += red[tid + st];
        __syncthreads();
    }
    if (tid == 0) {
        int tgt = targets[row];
        float v = 0.f;
        if (tgt != -1) v = m + logf(red[0]) - lr[tgt];
        nll[row] = v;
    }
}

__global__ void loss_final_kernel(const float* __restrict__ nll, const int* __restrict__ targets,
                                  float* __restrict__ out)
{
    int tid = threadIdx.x;
    float s = 0.f, cnt = 0.f;
    for (int i = tid; i < NTOK; i += 256) {
        if (targets[i] != -1) { s += nll[i]; cnt += 1.f; }
    }
    __shared__ float r1[256], r2[256];
    r1[tid] = s; r2[tid] = cnt;
    __syncthreads();
    for (int st = 128; st > 0; st >>= 1) {
        if (tid < st) { r1[tid] += r1[tid + st]; r2[tid] += r2[tid + st]; }
        __syncthreads();
    }
    if (tid == 0) out[0] = r1[0] / r2[0];
}

// ---------------- host orchestration ----------------
extern "C" void kernel_launch(void* const* d_in, const int* in_sizes, int n_in,
                              void* d_out, int out_size)
{
    const int*   idx        = (const int*)d_in[0];
    const int*   targets    = (const int*)d_in[1];
    const float* wte        = (const float*)d_in[2];
    const float* wpe        = (const float*)d_in[3];
    const float* ln1_w      = (const float*)d_in[4];
    const float* ln1_b      = (const float*)d_in[5];
    const float* attn_w     = (const float*)d_in[6];
    const float* attn_b     = (const float*)d_in[7];
    const float* proj_w     = (const float*)d_in[8];
    const float* proj_b     = (const float*)d_in[9];
    const float* ln2_w      = (const float*)d_in[10];
    const float* ln2_b      = (const float*)d_in[11];
    const float* fc_w       = (const float*)d_in[12];
    const float* fc_b       = (const float*)d_in[13];
    const float* mlp_w      = (const float*)d_in[14];
    const float* mlp_b      = (const float*)d_in[15];
    const float* thresholds = (const float*)d_in[16];
    const float* lnf_w      = (const float*)d_in[17];
    const float* lnf_b      = (const float*)d_in[18];

    float *x, *score, *am, *imp, *nll;
    bf16 *hh, *hl, *qh, *ql, *atth, *attl, *yh, *yl, *fch, *fcl;
    bf16 *awh, *awl, *pwh, *pwl, *fwh, *fwl, *mwh, *mwl, *wteh, *wtel;
    cudaGetSymbolAddress((void**)&x,     g_x);
    cudaGetSymbolAddress((void**)&score, g_score);
    cudaGetSymbolAddress((void**)&am,    g_am);
    cudaGetSymbolAddress((void**)&imp,   g_imp);
    cudaGetSymbolAddress((void**)&nll,   g_nll);
    cudaGetSymbolAddress((void**)&hh,    g_h_hi);   cudaGetSymbolAddress((void**)&hl, g_h_lo);
    cudaGetSymbolAddress((void**)&qh,    g_qkv_hi); cudaGetSymbolAddress((void**)&ql, g_qkv_lo);
    cudaGetSymbolAddress((void**)&atth,  g_att_hi); cudaGetSymbolAddress((void**)&attl, g_att_lo);
    cudaGetSymbolAddress((void**)&yh,    g_y_hi);   cudaGetSymbolAddress((void**)&yl, g_y_lo);
    cudaGetSymbolAddress((void**)&fch,   g_fc_hi);  cudaGetSymbolAddress((void**)&fcl, g_fc_lo);
    cudaGetSymbolAddress((void**)&awh,   g_aw_hi);  cudaGetSymbolAddress((void**)&awl, g_aw_lo);
    cudaGetSymbolAddress((void**)&pwh,   g_pw_hi);  cudaGetSymbolAddress((void**)&pwl, g_pw_lo);
    cudaGetSymbolAddress((void**)&fwh,   g_fw_hi);  cudaGetSymbolAddress((void**)&fwl, g_fw_lo);
    cudaGetSymbolAddress((void**)&mwh,   g_mw_hi);  cudaGetSymbolAddress((void**)&mwl, g_mw_lo);
    cudaGetSymbolAddress((void**)&wteh,  g_wte_hi); cudaGetSymbolAddress((void**)&wtel, g_wte_lo);

    float* out = (float*)d_out;

    const int SM_NT  = gemm_smem_bytes(false, 128);
    const int SM_T   = gemm_smem_bytes(true, 128);
    const int SM_N64 = gemm_smem_bytes(false, 64);

    static bool attr_done = false;
    if (!attr_done) {
        cudaFuncSetAttribute(gemm_bf3<false, 0, true, 128>, cudaFuncAttributeMaxDynamicSharedMemorySize, SM_NT);
        cudaFuncSetAttribute(gemm_bf3<false, 1, true, 128>, cudaFuncAttributeMaxDynamicSharedMemorySize, SM_NT);
        cudaFuncSetAttribute(gemm_bf3<false, 0, false, 128>, cudaFuncAttributeMaxDynamicSharedMemorySize, SM_NT);
        cudaFuncSetAttribute(gemm_bf3<true, 0, false, 128>, cudaFuncAttributeMaxDynamicSharedMemorySize, SM_T);
        cudaFuncSetAttribute(gemm_bf3<false, 0, true, 64>, cudaFuncAttributeMaxDynamicSharedMemorySize, SM_N64);
        attr_done = true;
    }

    // split all weights
    {
        int n;
        n = NLAYER * CDIM * C3 / 4;
        split_kernel<<<(n + 255) / 256, 256>>>((const float4*)attn_w, awh, awl, n);
        n = NLAYER * CDIM * CDIM / 4;
        split_kernel<<<(n + 255) / 256, 256>>>((const float4*)proj_w, pwh, pwl, n);
        n = NLAYER * CDIM * C4 / 4;
        split_kernel<<<(n + 255) / 256, 256>>>((const float4*)fc_w, fwh, fwl, n);
        n = NLAYER * C4 * CDIM / 4;
        split_kernel<<<(n + 255) / 256, 256>>>((const float4*)mlp_w, mwh, mwl, n);
        n = VOCAB * CDIM / 4;
        split_kernel<<<(n + 255) / 256, 256>>>((const float4*)wte, wteh, wtel, n);
    }

    embed_kernel<<<NTOK, 256>>>(idx, wte, wpe, x);
    init_am_kernel<<<NTOK / 256, 256>>>(am);

    for (int l = 0; l < NLAYER; l++) {
        ln_split_kernel<<<NTOK, 256>>>(x, ln1_w + (long)l * CDIM, ln1_b + (long)l * CDIM, hh, hl);

        gemm_bf3<false, 0, true, 128><<<dim3(C3 / 128, NTOK / BM, 1), 256, SM_NT>>>(
            hh, hl, CDIM, 0, 0,
            awh + (long)l * CDIM * C3, awl + (long)l * CDIM * C3, C3, 0, 0,
            attn_b + (long)l * C3, nullptr,
            nullptr, qh, ql, C3, 0, 0, C3, CDIM, 1, 0, 0);

        gemm_bf3<true, 0, false, 128><<<dim3(TSEQ / 128, TSEQ / BM, BBATCH * NHEAD), 256, SM_T>>>(
            qh, ql, C3, (long)TSEQ * C3, HSZ,
            qh + CDIM, ql + CDIM, C3, (long)TSEQ * C3, HSZ,
            nullptr, nullptr,
            score, nullptr, nullptr, TSEQ, (long)NHEAD * TSEQ * TSEQ, (long)TSEQ * TSEQ,
            TSEQ, HSZ, NHEAD, 1, 0);

        softmax_mask_kernel<<<BBATCH * NHEAD * TSEQ, 256>>>(score, am, atth, attl);

        zero_kernel<<<NTOK / 256, 256>>>(imp, NTOK);
        imp_reduce_kernel<<<dim3(BBATCH, TSEQ / 256, 16), 256>>>(atth, attl, imp);

        gemm_bf3<false, 0, true, 64><<<dim3(1, TSEQ / BM, BBATCH * NHEAD), 256, SM_N64>>>(
            atth, attl, TSEQ, (long)NHEAD * TSEQ * TSEQ, (long)TSEQ * TSEQ,
            qh + 2 * CDIM, ql + 2 * CDIM, C3, (long)TSEQ * C3, HSZ,
            nullptr, nullptr,
            nullptr, yh, yl, CDIM, (long)TSEQ * CDIM, HSZ,
            HSZ, TSEQ, NHEAD, 0, 1);

        gemm_bf3<false, 0, false, 128><<<dim3(CDIM / 128, NTOK / BM, 1), 256, SM_NT>>>(
            yh, yl, CDIM, 0, 0,
            pwh + (long)l * CDIM * CDIM, pwl + (long)l * CDIM * CDIM, CDIM, 0, 0,
            proj_b + (long)l * CDIM, x,
            x, nullptr, nullptr, CDIM, 0, 0, CDIM, CDIM, 1, 0, 0);

        prune_mask_kernel<<<NTOK / 256, 256>>>(imp, am, thresholds, l);
        scale_rows_kernel<<<NTOK, 256>>>(x, am);

        ln_split_kernel<<<NTOK, 256>>>(x, ln2_w + (long)l * CDIM, ln2_b + (long)l * CDIM, hh, hl);

        gemm_bf3<false, 1, true, 128><<<dim3(C4 / 128, NTOK / BM, 1), 256, SM_NT>>>(
            hh, hl, CDIM, 0, 0,
            fwh + (long)l * CDIM * C4, fwl + (long)l * CDIM * C4, C4, 0, 0,
            fc_b + (long)l * C4, nullptr,
            nullptr, fch, fcl, C4, 0, 0, C4, CDIM, 1, 0, 0);

        gemm_bf3<false, 0, false, 128><<<dim3(CDIM / 128, NTOK / BM, 1), 256, SM_NT>>>(
            fch, fcl, C4, 0, 0,
            mwh + (long)l * C4 * CDIM, mwl + (long)l * C4 * CDIM, CDIM, 0, 0,
            mlp_b + (long)l * CDIM, x,
            x, nullptr, nullptr, CDIM, 0, 0, CDIM, C4, 1, 0, 0);
    }

    ln_split_kernel<<<NTOK, 256>>>(x, lnf_w, lnf_b, hh, hl);

    // logits = h @ wte^T (fp32 out)  — VOCAB = 50304 = 393 * 128, exact
    gemm_bf3<true, 0, false, 128><<<dim3(VOCAB / 128, NTOK / BM, 1), 256, SM_T>>>(
        hh, hl, CDIM, 0, 0,
        wteh, wtel, CDIM, 0, 0,
        nullptr, nullptr,
        out, nullptr, nullptr, VOCAB, 0, 0, VOCAB, CDIM, 1, 0, 0);

    loss_row_kernel<<<NTOK, 256>>>(out, targets, nll);
    if ((long)out_size >= (long)NTOK * VOCAB + 1)
        loss_final_kernel<<<1, 256>>>(nll, targets, out + (long)NTOK * VOCAB);
}